// round 1
// baseline (speedup 1.0000x reference)
#include <cuda_runtime.h>
#include <math.h>

// Problem constants
#define T_   1024
#define B_   8
#define D_   1024
#define H_   16
#define DH_  64
#define FF_  4096
#define M_   (T_ * B_)          // 8192 rows
#define MD_  (8388608)          // M_ * D_
#define SCALE_ 0.125f           // 1/sqrt(64)
#define BG_  0.1f

// Scratch: 19 * MD floats (~637 MB) of static device memory (no allocs allowed).
// layout (units of MD floats):
// 0:xn 1:q 2:k 3:v 4:attn 5:y(src2) 6-8:yW0..2 9-11:xU0..2 12:src 13:sn 14:ffo 15-18:ff1
__device__ float g_buf[19ull * 8388608ull];

// ---------------------------------------------------------------------------
// LayerNorm: one block per row (D=1024), 256 threads
// ---------------------------------------------------------------------------
__global__ __launch_bounds__(256) void ln_kernel(
    const float* __restrict__ x, const float* __restrict__ g,
    const float* __restrict__ b, float* __restrict__ out)
{
    int row = blockIdx.x;
    const float* xr = x + (size_t)row * D_;
    float s = 0.f, s2 = 0.f;
    #pragma unroll
    for (int i = threadIdx.x; i < D_; i += 256) {
        float v = xr[i]; s += v; s2 += v * v;
    }
    __shared__ float sh[20];
    #pragma unroll
    for (int o = 16; o > 0; o >>= 1) {
        s  += __shfl_down_sync(0xffffffffu, s,  o);
        s2 += __shfl_down_sync(0xffffffffu, s2, o);
    }
    int warp = threadIdx.x >> 5, lane = threadIdx.x & 31;
    if (lane == 0) { sh[warp] = s; sh[warp + 8] = s2; }
    __syncthreads();
    if (threadIdx.x == 0) {
        float ts = 0.f, ts2 = 0.f;
        #pragma unroll
        for (int w = 0; w < 8; w++) { ts += sh[w]; ts2 += sh[w + 8]; }
        float mean = ts * (1.0f / D_);
        float var  = ts2 * (1.0f / D_) - mean * mean;
        sh[16] = mean;
        sh[17] = rsqrtf(var + 1e-5f);
    }
    __syncthreads();
    float mean = sh[16], inv = sh[17];
    float* orow = out + (size_t)row * D_;
    #pragma unroll
    for (int i = threadIdx.x; i < D_; i += 256)
        orow[i] = (xr[i] - mean) * inv * g[i] + b[i];
}

// ---------------------------------------------------------------------------
// SGEMM: C[M,N] = A[M,K] @ B[K,N] (+bias, optional relu), row-major.
// 128x128 tile, BK=8, 256 threads, 8x8 per-thread microtile.
// All dims divisible by 128/8 for our shapes.
// ---------------------------------------------------------------------------
__global__ __launch_bounds__(256) void sgemm_kernel(
    const float* __restrict__ A, const float* __restrict__ Bm,
    float* __restrict__ C, int M, int N, int K,
    const float* __restrict__ bias, int relu)
{
    __shared__ float As[8][128];
    __shared__ float Bs[8][128];
    const int tid  = threadIdx.x;
    const int trow = tid >> 4;          // 0..15
    const int tcol = tid & 15;          // 0..15
    const float* Ab = A  + (size_t)blockIdx.y * 128 * K;
    const float* Bb = Bm + (size_t)blockIdx.x * 128;
    const int arow = tid >> 1, acol = (tid & 1) * 4;
    const int brow = tid >> 5, bcol = (tid & 31) * 4;

    float acc[8][8];
    #pragma unroll
    for (int i = 0; i < 8; i++)
        #pragma unroll
        for (int j = 0; j < 8; j++) acc[i][j] = 0.f;

    for (int k0 = 0; k0 < K; k0 += 8) {
        float4 av = *(const float4*)(Ab + (size_t)arow * K + k0 + acol);
        As[acol + 0][arow] = av.x;
        As[acol + 1][arow] = av.y;
        As[acol + 2][arow] = av.z;
        As[acol + 3][arow] = av.w;
        *(float4*)&Bs[brow][bcol] =
            *(const float4*)(Bb + (size_t)(k0 + brow) * N + bcol);
        __syncthreads();
        #pragma unroll
        for (int kk = 0; kk < 8; kk++) {
            float4 a0 = *(float4*)&As[kk][trow * 8];
            float4 a1 = *(float4*)&As[kk][trow * 8 + 4];
            float4 b0 = *(float4*)&Bs[kk][tcol * 8];
            float4 b1 = *(float4*)&Bs[kk][tcol * 8 + 4];
            float ar[8] = {a0.x, a0.y, a0.z, a0.w, a1.x, a1.y, a1.z, a1.w};
            float br[8] = {b0.x, b0.y, b0.z, b0.w, b1.x, b1.y, b1.z, b1.w};
            #pragma unroll
            for (int i = 0; i < 8; i++)
                #pragma unroll
                for (int j = 0; j < 8; j++)
                    acc[i][j] = fmaf(ar[i], br[j], acc[i][j]);
        }
        __syncthreads();
    }

    int crow0 = blockIdx.y * 128 + trow * 8;
    int ccol0 = blockIdx.x * 128 + tcol * 8;
    #pragma unroll
    for (int i = 0; i < 8; i++) {
        float* cr = C + (size_t)(crow0 + i) * N + ccol0;
        float v[8];
        #pragma unroll
        for (int j = 0; j < 8; j++) {
            v[j] = acc[i][j];
            if (bias) v[j] += bias[ccol0 + j];
            if (relu) v[j] = fmaxf(v[j], 0.f);
        }
        *(float4*)(cr)     = make_float4(v[0], v[1], v[2], v[3]);
        *(float4*)(cr + 4) = make_float4(v[4], v[5], v[6], v[7]);
    }
}

// ---------------------------------------------------------------------------
// Causal flash attention.
// q,k,v layout: [T, B, H, DH] = row (t*B+b) of a [M,1024] matrix, col h*64+d.
// grid = (T/128, B*H), 128 threads; each thread owns one query row.
// Online softmax, K/V tiles (64 rows) staged in SMEM, broadcast reads.
// ---------------------------------------------------------------------------
__global__ __launch_bounds__(128) void attn_kernel(
    const float* __restrict__ q, const float* __restrict__ k,
    const float* __restrict__ v, float* __restrict__ o)
{
    __shared__ float Ks[64][64];
    __shared__ float Vs[64][64];
    const int bh = blockIdx.y;                       // b*H + h
    const int i  = blockIdx.x * 128 + threadIdx.x;   // query time index
    const float* qb = q + (size_t)bh * DH_;
    const float* kb = k + (size_t)bh * DH_;
    const float* vb = v + (size_t)bh * DH_;

    float qr[DH_];
    #pragma unroll
    for (int d = 0; d < DH_; d++)
        qr[d] = qb[(size_t)i * (B_ * H_ * DH_) + d] * SCALE_;

    float m = -INFINITY, l = 0.f;
    float acc[DH_];
    #pragma unroll
    for (int d = 0; d < DH_; d++) acc[d] = 0.f;

    const int jend = blockIdx.x * 128 + 127;         // max query index in block
    const int jr = threadIdx.x >> 1;
    const int c0 = (threadIdx.x & 1) * 32;

    for (int j0 = 0; j0 <= jend; j0 += 64) {
        // cooperative K/V tile load: 64 rows x 64 floats, half-row per thread
        const size_t gro = (size_t)(j0 + jr) * (B_ * H_ * DH_) + c0;
        #pragma unroll
        for (int c = 0; c < 32; c += 4) {
            *(float4*)&Ks[jr][c0 + c] = *(const float4*)&kb[gro + c];
            *(float4*)&Vs[jr][c0 + c] = *(const float4*)&vb[gro + c];
        }
        __syncthreads();

        int jn = i - j0 + 1;                          // causal: j <= i
        if (jn > 64) jn = 64;
        for (int jj = 0; jj < jn; jj++) {
            float s = 0.f;
            #pragma unroll
            for (int d = 0; d < DH_; d++) s = fmaf(qr[d], Ks[jj][d], s);
            float mn   = fmaxf(m, s);
            float corr = __expf(m - mn);              // 0 when m == -inf
            float p    = __expf(s - mn);
            l = l * corr + p;
            #pragma unroll
            for (int d = 0; d < DH_; d++)
                acc[d] = fmaf(acc[d], corr, p * Vs[jj][d]);
            m = mn;
        }
        __syncthreads();
    }

    float invl = 1.0f / l;
    float* ob = o + (size_t)i * (B_ * H_ * DH_) + (size_t)bh * DH_;
    #pragma unroll
    for (int d = 0; d < DH_; d++) ob[d] = acc[d] * invl;
}

// ---------------------------------------------------------------------------
// GRU gate elementwise:
// r = sig(yW0+xU0); z = sig(yW1+xU1+bz-BG); h = tanh(yW2 + r*xU2)
// out = (1-z)*x + z*h
// ---------------------------------------------------------------------------
__global__ __launch_bounds__(256) void gru_kernel(
    const float* __restrict__ x,
    const float* __restrict__ yW0, const float* __restrict__ yW1,
    const float* __restrict__ yW2,
    const float* __restrict__ xU0, const float* __restrict__ xU1,
    const float* __restrict__ xU2,
    const float* __restrict__ bz, float* __restrict__ out)
{
    int idx = blockIdx.x * 256 + threadIdx.x;
    int d = idx & (D_ - 1);
    float r = 1.0f / (1.0f + expf(-(yW0[idx] + xU0[idx])));
    float z = 1.0f / (1.0f + expf(-(yW1[idx] + xU1[idx] + bz[d] - BG_)));
    float h = tanhf(yW2[idx] + r * xU2[idx]);
    out[idx] = (1.0f - z) * x[idx] + z * h;
}

// ---------------------------------------------------------------------------
extern "C" void kernel_launch(void* const* d_in, const int* in_sizes, int n_in,
                              void* d_out, int out_size)
{
    const float* x     = (const float*)d_in[0];
    const float* Wq    = (const float*)d_in[1];
    const float* Wk    = (const float*)d_in[2];
    const float* Wv    = (const float*)d_in[3];
    const float* Wo    = (const float*)d_in[4];
    const float* ln1_g = (const float*)d_in[5];
    const float* ln1_b = (const float*)d_in[6];
    const float* W1    = (const float*)d_in[7];
    const float* b1    = (const float*)d_in[8];
    const float* W2    = (const float*)d_in[9];
    const float* b2    = (const float*)d_in[10];
    const float* ln2_g = (const float*)d_in[11];
    const float* ln2_b = (const float*)d_in[12];
    const float* g1W   = (const float*)d_in[13];
    const float* g1U   = (const float*)d_in[14];
    const float* g1bz  = (const float*)d_in[15];
    const float* g2W   = (const float*)d_in[16];
    const float* g2U   = (const float*)d_in[17];
    const float* g2bz  = (const float*)d_in[18];
    // d_in[19] = attn_mask: deterministic causal triu, applied analytically.
    float* out = (float*)d_out;

    float* buf = nullptr;
    cudaGetSymbolAddress((void**)&buf, g_buf);
    float* xn    = buf + 0ull  * MD_;
    float* q     = buf + 1ull  * MD_;
    float* k     = buf + 2ull  * MD_;
    float* v     = buf + 3ull  * MD_;
    float* attnb = buf + 4ull  * MD_;
    float* y     = buf + 5ull  * MD_;
    float* yW    = buf + 6ull  * MD_;   // 3 * MD
    float* xU    = buf + 9ull  * MD_;   // 3 * MD
    float* src   = buf + 12ull * MD_;
    float* sn    = buf + 13ull * MD_;
    float* ffo   = buf + 14ull * MD_;
    float* ff1   = buf + 15ull * MD_;   // 4 * MD (8192 x 4096)

    const dim3 gDD(D_ / 128, M_ / 128);     // (8, 64)  [8192x1024 out]
    const dim3 gDF(FF_ / 128, M_ / 128);    // (32, 64) [8192x4096 out]
    const size_t DD = (size_t)D_ * D_;

    // 1) LN1
    ln_kernel<<<M_, 256>>>(x, ln1_g, ln1_b, xn);
    // 2) QKV projections
    sgemm_kernel<<<gDD, 256>>>(xn, Wq, q, M_, D_, D_, nullptr, 0);
    sgemm_kernel<<<gDD, 256>>>(xn, Wk, k, M_, D_, D_, nullptr, 0);
    sgemm_kernel<<<gDD, 256>>>(xn, Wv, v, M_, D_, D_, nullptr, 0);
    // 3) causal attention
    attn_kernel<<<dim3(T_ / 128, B_ * H_), 128>>>(q, k, v, attnb);
    // 4) output projection
    sgemm_kernel<<<gDD, 256>>>(attnb, Wo, y, M_, D_, D_, nullptr, 0);
    // 5) GRU gate 1: y@W[i], x@U[i]
    for (int i = 0; i < 3; i++) {
        sgemm_kernel<<<gDD, 256>>>(y, g1W + i * DD, yW + (size_t)i * MD_,
                                   M_, D_, D_, nullptr, 0);
        sgemm_kernel<<<gDD, 256>>>(x, g1U + i * DD, xU + (size_t)i * MD_,
                                   M_, D_, D_, nullptr, 0);
    }
    gru_kernel<<<MD_ / 256, 256>>>(x, yW, yW + MD_, yW + 2ull * MD_,
                                   xU, xU + MD_, xU + 2ull * MD_, g1bz, src);
    // 6) LN2 + FFN
    ln_kernel<<<M_, 256>>>(src, ln2_g, ln2_b, sn);
    sgemm_kernel<<<gDF, 256>>>(sn, W1, ff1, M_, FF_, D_, b1, 1);
    sgemm_kernel<<<gDD, 256>>>(ff1, W2, ffo, M_, D_, FF_, b2, 0);
    // 7) GRU gate 2: ffo@W[i], src@U[i]
    for (int i = 0; i < 3; i++) {
        sgemm_kernel<<<gDD, 256>>>(ffo, g2W + i * DD, yW + (size_t)i * MD_,
                                   M_, D_, D_, nullptr, 0);
        sgemm_kernel<<<gDD, 256>>>(src, g2U + i * DD, xU + (size_t)i * MD_,
                                   M_, D_, D_, nullptr, 0);
    }
    gru_kernel<<<MD_ / 256, 256>>>(src, yW, yW + MD_, yW + 2ull * MD_,
                                   xU, xU + MD_, xU + 2ull * MD_, g2bz, out);
}

// round 4
// speedup vs baseline: 2.1464x; 2.1464x over previous
#include <cuda_runtime.h>
#include <cuda_bf16.h>
#include <math.h>
#include <stdint.h>

// Problem constants
#define T_   1024
#define B_   8
#define D_   1024
#define H_   16
#define DH_  64
#define FF_  4096
#define M_   (T_ * B_)          // 8192
#define MD_  (8388608)          // M_ * D_
#define SCALE_ 0.125f
#define BG_  0.1f

// fp32 scratch:
// 0:xn 1-3:qkv 4:attnb 5:y 6-8:yW 9-11:xU 12:src 13:sn 14:ffo 15-18:ff1
__device__ float g_buf[19ull * 8388608ull];
// bf16 split scratch
__device__ __nv_bfloat16 g_Ah[33554432];
__device__ __nv_bfloat16 g_Al[33554432];
__device__ __nv_bfloat16 g_Bh[4194304];
__device__ __nv_bfloat16 g_Bl[4194304];

// ---------------------------------------------------------------------------
// PTX helpers (baseline PTX only — compute_100 has no tcgen05)
// ---------------------------------------------------------------------------
__device__ __forceinline__ uint32_t smem_u32(const void* p) {
    uint32_t a;
    asm("{ .reg .u64 t; cvta.to.shared.u64 t, %1; cvt.u32.u64 %0, t; }"
        : "=r"(a) : "l"(p));
    return a;
}
__device__ __forceinline__ void cp16(uint32_t s, const void* g) {
    asm volatile("cp.async.cg.shared.global [%0], [%1], 16;" :: "r"(s), "l"(g));
}
__device__ __forceinline__ void cp_commit() {
    asm volatile("cp.async.commit_group;" ::: "memory");
}
__device__ __forceinline__ void cp_wait1() {
    asm volatile("cp.async.wait_group 1;" ::: "memory");
}
__device__ __forceinline__ void ldsm4(uint32_t (&r)[4], uint32_t addr) {
    asm volatile("ldmatrix.sync.aligned.m8n8.x4.shared.b16 {%0,%1,%2,%3}, [%4];"
        : "=r"(r[0]), "=r"(r[1]), "=r"(r[2]), "=r"(r[3]) : "r"(addr));
}
#define MMA(d, a, b) \
    asm volatile("mma.sync.aligned.m16n8k16.row.col.f32.bf16.bf16.f32 " \
        "{%0,%1,%2,%3}, {%4,%5,%6,%7}, {%8,%9}, {%0,%1,%2,%3};" \
        : "+f"((d)[0]), "+f"((d)[1]), "+f"((d)[2]), "+f"((d)[3]) \
        : "r"((a)[0]), "r"((a)[1]), "r"((a)[2]), "r"((a)[3]), \
          "r"((b)[0]), "r"((b)[1]))

// ---------------------------------------------------------------------------
// fp32 -> bf16 hi/lo split (elementwise, float4 vectorized)
// ---------------------------------------------------------------------------
__global__ __launch_bounds__(256) void splitA_kernel(
    const float* __restrict__ in, __nv_bfloat16* __restrict__ oh,
    __nv_bfloat16* __restrict__ ol, int n4)
{
    int i = blockIdx.x * 256 + threadIdx.x;
    if (i >= n4) return;
    float4 v = ((const float4*)in)[i];
    float vv[4] = {v.x, v.y, v.z, v.w};
    __nv_bfloat16 h[4], l[4];
    #pragma unroll
    for (int j = 0; j < 4; j++) {
        h[j] = __float2bfloat16_rn(vv[j]);
        l[j] = __float2bfloat16_rn(vv[j] - __bfloat162float(h[j]));
    }
    ((__nv_bfloat162*)oh)[2 * i]     = __nv_bfloat162(h[0], h[1]);
    ((__nv_bfloat162*)oh)[2 * i + 1] = __nv_bfloat162(h[2], h[3]);
    ((__nv_bfloat162*)ol)[2 * i]     = __nv_bfloat162(l[0], l[1]);
    ((__nv_bfloat162*)ol)[2 * i + 1] = __nv_bfloat162(l[2], l[3]);
}

// ---------------------------------------------------------------------------
// Weight transpose + split: in fp32 [K,N] -> out bf16 [N,K] hi/lo
// ---------------------------------------------------------------------------
__global__ __launch_bounds__(256) void transB_kernel(
    const float* __restrict__ in, __nv_bfloat16* __restrict__ oh,
    __nv_bfloat16* __restrict__ ol, int Kd, int Nd)
{
    __shared__ float t[32][33];
    int n0 = blockIdx.x * 32, k0 = blockIdx.y * 32;
    int tx = threadIdx.x, ty = threadIdx.y;      // (32, 8)
    #pragma unroll
    for (int j = 0; j < 32; j += 8)
        t[ty + j][tx] = in[(size_t)(k0 + ty + j) * Nd + n0 + tx];
    __syncthreads();
    #pragma unroll
    for (int j = 0; j < 32; j += 8) {
        float v = t[tx][ty + j];
        __nv_bfloat16 h = __float2bfloat16_rn(v);
        __nv_bfloat16 l = __float2bfloat16_rn(v - __bfloat162float(h));
        size_t o = (size_t)(n0 + ty + j) * Kd + k0 + tx;
        oh[o] = h; ol[o] = l;
    }
}

// ---------------------------------------------------------------------------
// bf16-split GEMM on mma.sync: C[M,N] = A[M,K] @ Bt[N,K]^T (fp32-accurate)
// 128x128x32 CTA tile, 8 warps (32x64 each), 3-stage cp.async pipeline.
// ---------------------------------------------------------------------------
#define BM 128
#define BN 128
#define BK 32
#define STAGES 3
#define AROW 40                             // padded row stride (bf16 elems)
#define MAT_BYTES (BM * AROW * 2)           // 10240
#define STAGE_BYTES (4 * MAT_BYTES)         // 40960
#define GEMM_SMEM (STAGES * STAGE_BYTES)    // 122880

__global__ __launch_bounds__(256) void mma_gemm(
    const __nv_bfloat16* __restrict__ Ah, const __nv_bfloat16* __restrict__ Al,
    const __nv_bfloat16* __restrict__ Bh, const __nv_bfloat16* __restrict__ Bl,
    float* __restrict__ C, int M, int N, int K,
    const float* __restrict__ bias, int relu)
{
    extern __shared__ char smem[];
    const uint32_t sbase = smem_u32(smem);
    const int tid = threadIdx.x, wid = tid >> 5, lane = tid & 31;
    const int wm = wid & 3, wn = wid >> 2;          // warp tile (32m x 64n)
    const size_t arow0 = (size_t)blockIdx.y * BM;
    const size_t brow0 = (size_t)blockIdx.x * BN;
    const __nv_bfloat16* srcs[4] = {
        Ah + arow0 * K, Al + arow0 * K, Bh + brow0 * K, Bl + brow0 * K };
    const int KT = K / BK;

    // per-thread cp.async mapping (2 x 16B per matrix per stage)
    const int crow0_ld = tid >> 2, c16 = tid & 3;

    // ldmatrix lane addressing
    const int lrowA = lane & 15;
    const int lcolA = (lane >> 4) * 8;
    const int lrowB = (lane & 7) + ((lane >> 4) << 3);
    const int lcolB = ((lane >> 3) & 1) * 8;

    float acc[2][8][4];
    #pragma unroll
    for (int i = 0; i < 2; i++)
        #pragma unroll
        for (int j = 0; j < 8; j++)
            #pragma unroll
            for (int q = 0; q < 4; q++) acc[i][j][q] = 0.f;

    auto load_stage = [&](int t) {
        uint32_t sb = sbase + (uint32_t)(t % STAGES) * STAGE_BYTES;
        size_t koff = (size_t)t * BK;
        #pragma unroll
        for (int m = 0; m < 4; m++) {
            const __nv_bfloat16* g = srcs[m] + koff;
            uint32_t sm = sb + m * MAT_BYTES;
            #pragma unroll
            for (int j = 0; j < 2; j++) {
                int row = crow0_ld + j * 64;
                cp16(sm + (uint32_t)(row * AROW + c16 * 8) * 2,
                     (const char*)(g + (size_t)row * K) + c16 * 16);
            }
        }
        cp_commit();
    };

    load_stage(0);
    load_stage(1);

    for (int t = 0; t < KT; t++) {
        cp_wait1();
        __syncthreads();
        if (t + STAGES - 1 < KT) load_stage(t + STAGES - 1);

        uint32_t sb  = sbase + (uint32_t)(t % STAGES) * STAGE_BYTES;
        uint32_t sAh = sb, sAl = sb + MAT_BYTES;
        uint32_t sBh = sb + 2 * MAT_BYTES, sBl = sb + 3 * MAT_BYTES;

        #pragma unroll
        for (int kk = 0; kk < BK; kk += 16) {
            uint32_t aH[2][4], aL[2][4], bH[8][2], bL[8][2];
            #pragma unroll
            for (int mi = 0; mi < 2; mi++) {
                uint32_t off =
                    (uint32_t)((wm * 32 + mi * 16 + lrowA) * AROW + kk + lcolA) * 2;
                ldsm4(aH[mi], sAh + off);
                ldsm4(aL[mi], sAl + off);
            }
            #pragma unroll
            for (int np = 0; np < 4; np++) {
                uint32_t off =
                    (uint32_t)((wn * 64 + np * 16 + lrowB) * AROW + kk + lcolB) * 2;
                uint32_t r[4];
                ldsm4(r, sBh + off);
                bH[2 * np][0] = r[0]; bH[2 * np][1] = r[1];
                bH[2 * np + 1][0] = r[2]; bH[2 * np + 1][1] = r[3];
                ldsm4(r, sBl + off);
                bL[2 * np][0] = r[0]; bL[2 * np][1] = r[1];
                bL[2 * np + 1][0] = r[2]; bL[2 * np + 1][1] = r[3];
            }
            #pragma unroll
            for (int mi = 0; mi < 2; mi++)
                #pragma unroll
                for (int ni = 0; ni < 8; ni++) {
                    MMA(acc[mi][ni], aH[mi], bH[ni]);
                    MMA(acc[mi][ni], aH[mi], bL[ni]);
                    MMA(acc[mi][ni], aL[mi], bH[ni]);
                }
        }
        __syncthreads();
    }

    // epilogue: registers -> GMEM (float2), fused bias/relu
    const int g = lane >> 2, tq = lane & 3;
    const int crow = blockIdx.y * BM + wm * 32;
    const int ccol = blockIdx.x * BN + wn * 64;
    #pragma unroll
    for (int mi = 0; mi < 2; mi++) {
        #pragma unroll
        for (int ni = 0; ni < 8; ni++) {
            int row = crow + mi * 16 + g;
            int col = ccol + ni * 8 + tq * 2;
            float2 v0 = make_float2(acc[mi][ni][0], acc[mi][ni][1]);
            float2 v1 = make_float2(acc[mi][ni][2], acc[mi][ni][3]);
            if (bias) {
                float2 bv = *(const float2*)(bias + col);
                v0.x += bv.x; v0.y += bv.y; v1.x += bv.x; v1.y += bv.y;
            }
            if (relu) {
                v0.x = fmaxf(v0.x, 0.f); v0.y = fmaxf(v0.y, 0.f);
                v1.x = fmaxf(v1.x, 0.f); v1.y = fmaxf(v1.y, 0.f);
            }
            *(float2*)&C[(size_t)row * N + col]       = v0;
            *(float2*)&C[(size_t)(row + 8) * N + col] = v1;
        }
    }
}

// ---------------------------------------------------------------------------
// LayerNorm
// ---------------------------------------------------------------------------
__global__ __launch_bounds__(256) void ln_kernel(
    const float* __restrict__ x, const float* __restrict__ g,
    const float* __restrict__ b, float* __restrict__ out)
{
    int row = blockIdx.x;
    const float* xr = x + (size_t)row * D_;
    float s = 0.f, s2 = 0.f;
    #pragma unroll
    for (int i = threadIdx.x; i < D_; i += 256) {
        float v = xr[i]; s += v; s2 += v * v;
    }
    __shared__ float sh[20];
    #pragma unroll
    for (int o = 16; o > 0; o >>= 1) {
        s  += __shfl_down_sync(0xffffffffu, s,  o);
        s2 += __shfl_down_sync(0xffffffffu, s2, o);
    }
    int warp = threadIdx.x >> 5, lane = threadIdx.x & 31;
    if (lane == 0) { sh[warp] = s; sh[warp + 8] = s2; }
    __syncthreads();
    if (threadIdx.x == 0) {
        float ts = 0.f, ts2 = 0.f;
        #pragma unroll
        for (int w = 0; w < 8; w++) { ts += sh[w]; ts2 += sh[w + 8]; }
        float mean = ts * (1.0f / D_);
        float var  = ts2 * (1.0f / D_) - mean * mean;
        sh[16] = mean;
        sh[17] = rsqrtf(var + 1e-5f);
    }
    __syncthreads();
    float mean = sh[16], inv = sh[17];
    float* orow = out + (size_t)row * D_;
    #pragma unroll
    for (int i = threadIdx.x; i < D_; i += 256)
        orow[i] = (xr[i] - mean) * inv * g[i] + b[i];
}

// ---------------------------------------------------------------------------
// Causal flash attention; qkv packed [M, 3072] (row = t*B + b):
// q cols [0,1024), k cols [1024,2048), v cols [2048,3072); head h -> h*64.
// Output attnb [M, 1024].
// ---------------------------------------------------------------------------
#define QKV_S 3072
__global__ __launch_bounds__(128) void attn_kernel(
    const float* __restrict__ qkv, float* __restrict__ o)
{
    __shared__ float Ks[64][64];
    __shared__ float Vs[64][64];
    const int bh = blockIdx.y;
    const int bb = bh >> 4, hh = bh & 15;            // batch, head
    const int i  = blockIdx.x * 128 + threadIdx.x;   // query time index
    const size_t colq = (size_t)hh * DH_;

    float qr[DH_];
    #pragma unroll
    for (int d = 0; d < DH_; d++)
        qr[d] = qkv[(size_t)(i * B_ + bb) * QKV_S + colq + d] * SCALE_;

    float m = -INFINITY, l = 0.f;
    float acc[DH_];
    #pragma unroll
    for (int d = 0; d < DH_; d++) acc[d] = 0.f;

    const int jend = blockIdx.x * 128 + 127;
    const int jr = threadIdx.x >> 1;
    const int c0 = (threadIdx.x & 1) * 32;

    for (int j0 = 0; j0 <= jend; j0 += 64) {
        // K/V tile rows j0..j0+63, cooperative load (half-row per thread)
        const size_t gro = (size_t)((j0 + jr) * B_ + bb) * QKV_S + colq + c0;
        #pragma unroll
        for (int c = 0; c < 32; c += 4) {
            *(float4*)&Ks[jr][c0 + c] = *(const float4*)&qkv[gro + 1024 + c];
            *(float4*)&Vs[jr][c0 + c] = *(const float4*)&qkv[gro + 2048 + c];
        }
        __syncthreads();
        int jn = i - j0 + 1;
        if (jn > 64) jn = 64;
        for (int jj = 0; jj < jn; jj++) {
            float s = 0.f;
            #pragma unroll
            for (int d = 0; d < DH_; d++) s = fmaf(qr[d], Ks[jj][d], s);
            float mn   = fmaxf(m, s);
            float corr = __expf(m - mn);
            float p    = __expf(s - mn);
            l = l * corr + p;
            #pragma unroll
            for (int d = 0; d < DH_; d++)
                acc[d] = fmaf(acc[d], corr, p * Vs[jj][d]);
            m = mn;
        }
        __syncthreads();
    }
    float invl = 1.0f / l;
    float* ob = o + (size_t)(i * B_ + bb) * (H_ * DH_) + colq;
    #pragma unroll
    for (int d = 0; d < DH_; d++) ob[d] = acc[d] * invl;
}

// ---------------------------------------------------------------------------
// GRU gate: yW/xU packed [M, 3072] (r|z|g per row)
// ---------------------------------------------------------------------------
__global__ __launch_bounds__(256) void gru_kernel(
    const float* __restrict__ x,
    const float* __restrict__ yW, const float* __restrict__ xU,
    const float* __restrict__ bz, float* __restrict__ out)
{
    int idx = blockIdx.x * 256 + threadIdx.x;
    int row = idx >> 10, d = idx & (D_ - 1);
    size_t b = (size_t)row * 3072 + d;
    float r = 1.0f / (1.0f + expf(-(yW[b] + xU[b])));
    float z = 1.0f / (1.0f + expf(-(yW[b + 1024] + xU[b + 1024] + bz[d] - BG_)));
    float h = tanhf(yW[b + 2048] + r * xU[b + 2048]);
    out[idx] = (1.0f - z) * x[idx] + z * h;
}

// ---------------------------------------------------------------------------
static void conv_A(const float* src, __nv_bfloat16* ah, __nv_bfloat16* al, size_t n) {
    int n4 = (int)(n >> 2);
    splitA_kernel<<<(n4 + 255) / 256, 256>>>(src, ah, al, n4);
}
static void conv_B(const float* w, __nv_bfloat16* bh, __nv_bfloat16* bl, int K, int N,
                   size_t outRowOff) {
    dim3 g(N / 32, K / 32), b(32, 8);
    transB_kernel<<<g, b>>>(w, bh + outRowOff * K, bl + outRowOff * K, K, N);
}

extern "C" void kernel_launch(void* const* d_in, const int* in_sizes, int n_in,
                              void* d_out, int out_size)
{
    const float* x     = (const float*)d_in[0];
    const float* Wq    = (const float*)d_in[1];
    const float* Wk    = (const float*)d_in[2];
    const float* Wv    = (const float*)d_in[3];
    const float* Wo    = (const float*)d_in[4];
    const float* ln1_g = (const float*)d_in[5];
    const float* ln1_b = (const float*)d_in[6];
    const float* W1    = (const float*)d_in[7];
    const float* b1    = (const float*)d_in[8];
    const float* W2    = (const float*)d_in[9];
    const float* b2    = (const float*)d_in[10];
    const float* ln2_g = (const float*)d_in[11];
    const float* ln2_b = (const float*)d_in[12];
    const float* g1W   = (const float*)d_in[13];
    const float* g1U   = (const float*)d_in[14];
    const float* g1bz  = (const float*)d_in[15];
    const float* g2W   = (const float*)d_in[16];
    const float* g2U   = (const float*)d_in[17];
    const float* g2bz  = (const float*)d_in[18];
    float* out = (float*)d_out;

    float* buf = nullptr;
    cudaGetSymbolAddress((void**)&buf, g_buf);
    __nv_bfloat16 *Ah, *Al, *Bh, *Bl;
    cudaGetSymbolAddress((void**)&Ah, g_Ah);
    cudaGetSymbolAddress((void**)&Al, g_Al);
    cudaGetSymbolAddress((void**)&Bh, g_Bh);
    cudaGetSymbolAddress((void**)&Bl, g_Bl);

    float* xn    = buf + 0ull  * MD_;
    float* qkv   = buf + 1ull  * MD_;   // [M, 3072]
    float* attnb = buf + 4ull  * MD_;
    float* y     = buf + 5ull  * MD_;
    float* yW    = buf + 6ull  * MD_;   // [M, 3072]
    float* xU    = buf + 9ull  * MD_;   // [M, 3072]
    float* src   = buf + 12ull * MD_;
    float* sn    = buf + 13ull * MD_;
    float* ffo   = buf + 14ull * MD_;
    float* ff1   = buf + 15ull * MD_;   // [M, 4096]

    cudaFuncSetAttribute(mma_gemm, cudaFuncAttributeMaxDynamicSharedMemorySize,
                         GEMM_SMEM);

    const size_t DD = (size_t)D_ * D_;
    const dim3 g3(3072 / 128, M_ / 128);
    const dim3 g1k(1024 / 128, M_ / 128);
    const dim3 g4k(4096 / 128, M_ / 128);

    // --- LN1 + QKV (fused N=3072) ---
    ln_kernel<<<M_, 256>>>(x, ln1_g, ln1_b, xn);
    conv_A(xn, Ah, Al, (size_t)MD_);
    conv_B(Wq, Bh, Bl, D_, D_, 0);
    conv_B(Wk, Bh, Bl, D_, D_, 1024);
    conv_B(Wv, Bh, Bl, D_, D_, 2048);
    mma_gemm<<<g3, 256, GEMM_SMEM>>>(Ah, Al, Bh, Bl, qkv, M_, 3072, D_, nullptr, 0);

    // --- attention ---
    attn_kernel<<<dim3(T_ / 128, B_ * H_), 128>>>(qkv, attnb);

    // --- output projection ---
    conv_A(attnb, Ah, Al, (size_t)MD_);
    conv_B(Wo, Bh, Bl, D_, D_, 0);
    mma_gemm<<<g1k, 256, GEMM_SMEM>>>(Ah, Al, Bh, Bl, y, M_, 1024, D_, nullptr, 0);

    // --- GRU gate 1 ---
    conv_A(y, Ah, Al, (size_t)MD_);
    for (int i = 0; i < 3; i++) conv_B(g1W + i * DD, Bh, Bl, D_, D_, (size_t)i * 1024);
    mma_gemm<<<g3, 256, GEMM_SMEM>>>(Ah, Al, Bh, Bl, yW, M_, 3072, D_, nullptr, 0);
    conv_A(x, Ah, Al, (size_t)MD_);
    for (int i = 0; i < 3; i++) conv_B(g1U + i * DD, Bh, Bl, D_, D_, (size_t)i * 1024);
    mma_gemm<<<g3, 256, GEMM_SMEM>>>(Ah, Al, Bh, Bl, xU, M_, 3072, D_, nullptr, 0);
    gru_kernel<<<MD_ / 256, 256>>>(x, yW, xU, g1bz, src);

    // --- LN2 + FFN ---
    ln_kernel<<<M_, 256>>>(src, ln2_g, ln2_b, sn);
    conv_A(sn, Ah, Al, (size_t)MD_);
    conv_B(W1, Bh, Bl, D_, FF_, 0);
    mma_gemm<<<g4k, 256, GEMM_SMEM>>>(Ah, Al, Bh, Bl, ff1, M_, 4096, D_, b1, 1);
    conv_A(ff1, Ah, Al, (size_t)M_ * FF_);
    conv_B(W2, Bh, Bl, FF_, D_, 0);
    mma_gemm<<<g1k, 256, GEMM_SMEM>>>(Ah, Al, Bh, Bl, ffo, M_, 1024, FF_, b2, 0);

    // --- GRU gate 2 ---
    conv_A(ffo, Ah, Al, (size_t)MD_);
    for (int i = 0; i < 3; i++) conv_B(g2W + i * DD, Bh, Bl, D_, D_, (size_t)i * 1024);
    mma_gemm<<<g3, 256, GEMM_SMEM>>>(Ah, Al, Bh, Bl, yW, M_, 3072, D_, nullptr, 0);
    conv_A(src, Ah, Al, (size_t)MD_);
    for (int i = 0; i < 3; i++) conv_B(g2U + i * DD, Bh, Bl, D_, D_, (size_t)i * 1024);
    mma_gemm<<<g3, 256, GEMM_SMEM>>>(Ah, Al, Bh, Bl, xU, M_, 3072, D_, nullptr, 0);
    gru_kernel<<<MD_ / 256, 256>>>(src, yW, xU, g2bz, out);
}